// round 7
// baseline (speedup 1.0000x reference)
#include <cuda_runtime.h>

#define TT 8192
#define H 512
#define NCTA 64
#define NTHREADS 256
#define FULLMASK 0xffffffffu

typedef unsigned long long u64;

// ---------------- static scratch (no allocations) ----------------
__device__ float g_hist1[TT * H];     // layer-0 h history (append-only, 16 MB)
__device__ float g_hist2[TT * H];     // layer-1 h history (append-only, 16 MB)
__device__ float g_hfinal[H];         // h2[T-1] for MLP head
__device__ unsigned g_ctr0;           // barrier counters (one hot line each)
__device__ unsigned g_ctr1;

// ---------------- helpers ----------------
struct ULL2 { u64 x, y; };

__device__ __forceinline__ ULL2 ldg2(const float* p) {   // 4 floats -> 2 packed f32x2
    ULL2 v; asm("ld.global.nc.v2.u64 {%0,%1},[%2];" : "=l"(v.x), "=l"(v.y) : "l"(p)); return v;
}
__device__ __forceinline__ ULL2 ldcg2(const float* p) {  // L2-coherent
    ULL2 v; asm volatile("ld.global.cg.v2.u64 {%0,%1},[%2];" : "=l"(v.x), "=l"(v.y) : "l"(p)); return v;
}
__device__ __forceinline__ void unpack2(u64 v, float& lo, float& hi) {
    asm("mov.b64 {%0,%1},%2;" : "=f"(lo), "=f"(hi) : "l"(v));
}
__device__ __forceinline__ void fma2(u64& acc, u64 a, u64 b) {   // 2 MACs/instr
    asm("fma.rn.f32x2 %0,%1,%2,%0;" : "+l"(acc) : "l"(a), "l"(b));
}
__device__ __forceinline__ unsigned ldacq(const unsigned* p) {
    unsigned v; asm volatile("ld.acquire.gpu.u32 %0,[%1];" : "=r"(v) : "l"(p)); return v;
}
__device__ __forceinline__ void redadd(unsigned* p) {
    asm volatile("red.relaxed.gpu.global.add.u32 [%0],1;" :: "l"(p));
}
__device__ __forceinline__ void stcgf(float* p, float v) {
    asm volatile("st.global.cg.f32 [%0],%1;" :: "l"(p), "f"(v));
}
__device__ __forceinline__ float tanhfast(float x) {
    float y; asm("tanh.approx.f32 %0,%1;" : "=f"(y) : "f"(x)); return y;
}
__device__ __forceinline__ float sigfast(float x) { return 0.5f * tanhfast(0.5f * x) + 0.5f; }

__global__ void init_kernel() { if (threadIdx.x == 0) { g_ctr0 = 0u; g_ctr1 = 0u; } }

// ---------------- persistent LSTM layer (counter barrier + slim compute) ----------------
// 64 CTAs x 256 threads, single wave. Warp wu owns output j = b*8+wu
// (gate rows {j, H+j, 2H+j, 3H+j}); lane l: sec = l>>3 (i/f/g/o), cg = l&7.
template <int LAYER>
__global__ void __launch_bounds__(NTHREADS, 1) lstm_kernel(
    const float* __restrict__ x,      // layer 0 only: input_seq [T] (NC=1)
    const float* __restrict__ w_ih, const float* __restrict__ w_hh,
    const float* __restrict__ b_ih, const float* __restrict__ b_hh)
{
    const int tid = threadIdx.x;
    const int wu  = tid >> 5;
    const int l   = tid & 31;
    const int cg  = l & 7;
    const int b   = blockIdx.x;
    const int j   = b * 8 + wu;
    const int row = (l >> 3) * H + j;
    const int coff = cg * 64;

    float* const hist = (LAYER == 0) ? g_hist1 : g_hist2;
    unsigned* const ctr = (LAYER == 0) ? &g_ctr0 : &g_ctr1;

    __shared__ float sx[(LAYER == 0) ? TT : 1];
    if (LAYER == 0) for (int i = tid; i < TT; i += NTHREADS) sx[i] = x[i];

    // recurrent weights -> registers (64 floats = 32 packed f32x2)
    u64 rw[32];
    {
        const float* p = w_hh + (size_t)row * H + coff;
#pragma unroll
        for (int k = 0; k < 16; k++) { ULL2 v = ldg2(p + 4 * k); rw[2*k] = v.x; rw[2*k+1] = v.y; }
    }
    u64 riw[32];                                   // layer-1 input weights (64 more regs)
    if (LAYER == 1) {
        const float* p = w_ih + (size_t)row * H + coff;
#pragma unroll
        for (int k = 0; k < 16; k++) { ULL2 v = ldg2(p + 4 * k); riw[2*k] = v.x; riw[2*k+1] = v.y; }
    }

    const float bi = b_ih[j]       + b_hh[j];
    const float bf = b_ih[H + j]   + b_hh[H + j];
    const float bg = b_ih[2*H + j] + b_hh[2*H + j];
    const float bo = b_ih[3*H + j] + b_hh[3*H + j];
    float wxi = 0.f, wxf = 0.f, wxg = 0.f, wxo = 0.f;   // NC = 1
    if (LAYER == 0) { wxi = w_ih[j]; wxf = w_ih[H + j]; wxg = w_ih[2*H + j]; wxo = w_ih[3*H + j]; }

    float c = 0.0f;   // cell state (replicated across lanes; identical inputs)
    __syncthreads();

    for (int t = 0; t < TT; t++) {
        // ---- barrier: all CTAs published h(t-1)
        if (t > 0) {
            if (tid == 0) {
                const unsigned tgt = (unsigned)(NCTA * t);
                while (ldacq(ctr) < tgt) {}
            }
            __syncthreads();
        }

        u64 a0 = 0ull, a1 = 0ull;
        // layer 1: input projection W_ih . h1[t] (h1 from previous kernel: stable,
        // no sync needed; loads pipeline with the recurrent loads below)
        if (LAYER == 1) {
            const float* hp = g_hist1 + (size_t)t * H + coff;
#pragma unroll
            for (int k = 0; k < 16; k++) {
                ULL2 hv = ldg2(hp + 4 * k);
                fma2(a0, riw[2*k], hv.x); fma2(a1, riw[2*k+1], hv.y);
            }
        }
        // recurrent term W_hh . h(t-1)
        if (t > 0) {
            const float* hb = hist + (size_t)(t - 1) * H + coff;
#pragma unroll
            for (int k = 0; k < 16; k++) {
                ULL2 hv = ldcg2(hb + 4 * k);
                fma2(a0, rw[2*k], hv.x); fma2(a1, rw[2*k+1], hv.y);
            }
        }

        // ---- warp-local reduce: row sum for this lane's gate row
        float p0, p1, q0, q1;
        unpack2(a0, p0, p1); unpack2(a1, q0, q1);
        float s = (p0 + p1) + (q0 + q1);
        s += __shfl_xor_sync(FULLMASK, s, 1);
        s += __shfl_xor_sync(FULLMASK, s, 2);
        s += __shfl_xor_sync(FULLMASK, s, 4);
        float iv = __shfl_sync(FULLMASK, s, cg);
        float fv = __shfl_sync(FULLMASK, s, 8 | cg);
        float gv = __shfl_sync(FULLMASK, s, 16 | cg);
        float ov = __shfl_sync(FULLMASK, s, 24 | cg);
        if (LAYER == 0) {
            const float xt = sx[t];
            iv += bi + wxi * xt; fv += bf + wxf * xt;
            gv += bg + wxg * xt; ov += bo + wxo * xt;
        } else {
            iv += bi; fv += bf; gv += bg; ov += bo;
        }
        float ii = sigfast(iv), ff = sigfast(fv), gg = tanhfast(gv), oo = sigfast(ov);
        c = ff * c + ii * gg;
        float hn = oo * tanhfast(c);

        if (l == 0) {
            stcgf(hist + (size_t)t * H + j, hn);            // append h(t)
            if (LAYER == 1 && t == TT - 1) stcgf(g_hfinal + j, hn);
        }
        __syncthreads();                                     // all 8 h stores issued
        if (tid == 0) { __threadfence(); redadd(ctr); }      // proven arrive pattern
    }
}

// ---------------- MLP head on h2[T-1] ----------------
__global__ void head_kernel(const float* __restrict__ w1, const float* __restrict__ b1,
                            const float* __restrict__ w2, const float* __restrict__ b2,
                            float* __restrict__ out)
{
    __shared__ float y1[32];
    const int tid = threadIdx.x, w = tid >> 5, l = tid & 31;
    for (int r = w; r < 20; r += 8) {
        float acc = 0.0f;
        for (int k = l; k < H; k += 32) acc += g_hfinal[k] * w1[r * H + k];
#pragma unroll
        for (int off = 16; off; off >>= 1) acc += __shfl_xor_sync(FULLMASK, acc, off);
        if (l == 0) y1[r] = acc + b1[r];
    }
    __syncthreads();
    if (tid == 0) {
        float o = b2[0];
#pragma unroll
        for (int r = 0; r < 20; r++) o += y1[r] * w2[r];
        out[0] = o;
    }
}

extern "C" void kernel_launch(void* const* d_in, const int* in_sizes, int n_in,
                              void* d_out, int out_size)
{
    const float* x    = (const float*)d_in[0];
    const float* wih0 = (const float*)d_in[1];
    const float* whh0 = (const float*)d_in[2];
    const float* bih0 = (const float*)d_in[3];
    const float* bhh0 = (const float*)d_in[4];
    const float* wih1 = (const float*)d_in[5];
    const float* whh1 = (const float*)d_in[6];
    const float* bih1 = (const float*)d_in[7];
    const float* bhh1 = (const float*)d_in[8];
    const float* w1   = (const float*)d_in[9];
    const float* b1   = (const float*)d_in[10];
    const float* w2   = (const float*)d_in[11];
    const float* b2   = (const float*)d_in[12];
    float* out = (float*)d_out;

    init_kernel<<<1, 32>>>();
    lstm_kernel<0><<<NCTA, NTHREADS>>>(x, wih0, whh0, bih0, bhh0);
    lstm_kernel<1><<<NCTA, NTHREADS>>>(nullptr, wih1, whh1, bih1, bhh1);
    head_kernel<<<1, 256>>>(w1, b1, w2, b2, out);
}

// round 8
// speedup vs baseline: 3.3182x; 3.3182x over previous
#include <cuda_runtime.h>

#define TT 8192
#define H 512
#define NCTA 64
#define NTHREADS 256
#define HPC 8          // h outputs per CTA
#define NCTR 8         // barrier counters (CTA b -> counter b&7)
#define PADC 32        // 32 uints = one 128B line per counter
#define FULLMASK 0xffffffffu

// Static scratch (no allocations allowed)
__device__ float g_h1[TT * H];       // layer-0 hidden states history (16 MB)
__device__ float g_hbuf[2][H];       // double-buffered h exchange (hot 4KB)
__device__ float g_hfinal[H];        // final h2
__device__ unsigned g_bar8[NCTR * PADC];   // 8 padded barrier counters

// ---------- helpers ----------
__device__ __forceinline__ unsigned long long pack2(float lo, float hi) {
    unsigned long long r;
    asm("mov.b64 %0,{%1,%2};" : "=l"(r) : "f"(lo), "f"(hi));
    return r;
}
__device__ __forceinline__ void unpack2(unsigned long long v, float& lo, float& hi) {
    asm("mov.b64 {%0,%1},%2;" : "=f"(lo), "=f"(hi) : "l"(v));
}
// packed fp32x2 FMA: 2 MACs per instruction (PTX-only on Blackwell)
__device__ __forceinline__ void fma2(unsigned long long& acc, unsigned long long a, unsigned long long b) {
    asm("fma.rn.f32x2 %0,%1,%2,%0;" : "+l"(acc) : "l"(a), "l"(b));
}
__device__ __forceinline__ float4 ldcg4(const float4* p) {
    float4 v;
    asm volatile("ld.global.cg.v4.f32 {%0,%1,%2,%3},[%4];"
                 : "=f"(v.x), "=f"(v.y), "=f"(v.z), "=f"(v.w) : "l"(p));
    return v;
}
__device__ __forceinline__ unsigned ldacq(const unsigned* p) {
    unsigned v;
    asm volatile("ld.acquire.gpu.u32 %0,[%1];" : "=r"(v) : "l"(p));
    return v;
}
__device__ __forceinline__ float tanhfast(float x) {
    float y; asm("tanh.approx.f32 %0,%1;" : "=f"(y) : "f"(x)); return y;
}
__device__ __forceinline__ float sigfast(float x) { return 0.5f * tanhfast(0.5f * x) + 0.5f; }

// ---------- init: reset barrier counters + h double buffer ----------
__global__ void init_kernel() {
    int t = threadIdx.x;
    if (t < NCTR * PADC) g_bar8[t] = 0u;
    for (int i = t; i < 2 * H; i += blockDim.x) ((float*)g_hbuf)[i] = 0.0f;
}

// ---------- persistent LSTM layer (R1 structure, 8-way barrier + fast gates) ----------
// 64 CTAs x 256 threads. CTA b owns h indices [b*8, b*8+8) -> 32 gate rows.
// Thread layout: warp w covers h columns [w*64, w*64+64); lane l = local gate row.
// lane 0..7 = i rows, 8..15 = f, 16..23 = g, 24..31 = o.
template <int LAYER>
__global__ void __launch_bounds__(NTHREADS, 1) lstm_kernel(
    const float* __restrict__ x,      // layer0: input_seq [T] (NC=1). layer1: unused
    const float* __restrict__ w_ih,   // layer0: [2048,1]; layer1: [2048,512]
    const float* __restrict__ w_hh,   // [2048,512]
    const float* __restrict__ b_ih,   // [2048]
    const float* __restrict__ b_hh)   // [2048]
{
    const int tid = threadIdx.x;
    const int w = tid >> 5;           // warp id 0..7 (column chunk)
    const int l = tid & 31;           // lane = local gate row 0..31
    const int b = blockIdx.x;
    const int sec = l >> 3;           // 0:i 1:f 2:g 3:o
    const int j8 = l & 7;
    const int grow = sec * H + b * HPC + j8;  // global gate row

    __shared__ float red[8][33];
    __shared__ float sx[(LAYER == 0) ? TT : 1];

    if (LAYER == 0) {
        for (int i = tid; i < TT; i += NTHREADS) sx[i] = x[i];
    }

    // Preload recurrent weights into registers (64 floats/thread per matrix)
    unsigned long long whh[32];
    {
        const float* wr = w_hh + (size_t)grow * H + w * 64;
#pragma unroll
        for (int k = 0; k < 16; k++) {
            float4 v = *(const float4*)(wr + 4 * k);
            whh[2 * k] = pack2(v.x, v.y);
            whh[2 * k + 1] = pack2(v.z, v.w);
        }
    }
    unsigned long long wihr[32];
    if (LAYER == 1) {
        const float* wr = w_ih + (size_t)grow * H + w * 64;
#pragma unroll
        for (int k = 0; k < 16; k++) {
            float4 v = *(const float4*)(wr + 4 * k);
            wihr[2 * k] = pack2(v.x, v.y);
            wihr[2 * k + 1] = pack2(v.z, v.w);
        }
    }
    const float bias = b_ih[grow] + b_hh[grow];
    const float wx = (LAYER == 0) ? w_ih[grow] : 0.0f;  // NC = 1
    float c = 0.0f;                                      // cell state (lanes 0..7 of warp 0)
    __syncthreads();

    for (int t = 0; t < TT; t++) {
        const int p = t & 1;

        // --- mat-vec: acc = W_hh[row, wcols] . h_prev[wcols] (+ W_ih . h1[t] for layer 1)
        unsigned long long a0 = 0ull, a1 = 0ull;  // bits 0 == (0.f, 0.f)
        const float4* hb = ((const float4*)g_hbuf[p]) + w * 16;
#pragma unroll
        for (int k = 0; k < 16; k++) {
            float4 hv = ldcg4(hb + k);
            fma2(a0, whh[2 * k], pack2(hv.x, hv.y));
            fma2(a1, whh[2 * k + 1], pack2(hv.z, hv.w));
        }
        if (LAYER == 1) {
            const float4* h1p = ((const float4*)g_h1) + (size_t)t * (H / 4) + w * 16;
#pragma unroll
            for (int k = 0; k < 16; k++) {
                float4 hv = __ldg(h1p + k);
                fma2(a0, wihr[2 * k], pack2(hv.x, hv.y));
                fma2(a1, wihr[2 * k + 1], pack2(hv.z, hv.w));
            }
        }
        float lo0, hi0, lo1, hi1;
        unpack2(a0, lo0, hi0);
        unpack2(a1, lo1, hi1);
        red[w][l] = (lo0 + hi0) + (lo1 + hi1);
        __syncthreads();

        if (w == 0) {
            float s = red[0][l];
#pragma unroll
            for (int q = 1; q < 8; q++) s += red[q][l];
            float gv = s + bias;
            if (LAYER == 0) gv += sx[t] * wx;
            // gather f/g/o onto the i-lane for the same j
            float fv = __shfl_sync(FULLMASK, gv, l + 8);
            float gg = __shfl_sync(FULLMASK, gv, l + 16);
            float ov = __shfl_sync(FULLMASK, gv, l + 24);
            if (l < 8) {
                float iv = sigfast(gv);
                float ff = sigfast(fv);
                float gt = tanhfast(gg);
                float oo = sigfast(ov);
                c = ff * c + iv * gt;
                float hn = oo * tanhfast(c);
                int hj = b * HPC + l;
                g_hbuf[p ^ 1][hj] = hn;
                if (LAYER == 0) g_h1[(size_t)t * H + hj] = hn;
                else if (t == TT - 1) g_hfinal[hj] = hn;
            }
            __syncwarp();
            if (l == 0) {
                __threadfence();                             // make h stores visible
                atomicAdd(&g_bar8[(b & 7) * PADC], 1u);      // arrive (8-way split)
            }
        }
        // global barrier: wait until all 8 counters reach 8*(t+1) (warp 0 polls)
        if (tid < 32) {
            const unsigned tgt = 8u * (unsigned)(t + 1);
            const unsigned* cp = &g_bar8[(l & 7) * PADC];
            for (;;) {
                unsigned v = ldacq(cp);
                if (__all_sync(FULLMASK, v >= tgt)) break;
            }
        }
        __syncthreads();
    }
}

// ---------- MLP head on final h2 ----------
__global__ void head_kernel(const float* __restrict__ w1, const float* __restrict__ b1,
                            const float* __restrict__ w2, const float* __restrict__ b2,
                            float* __restrict__ out)
{
    __shared__ float y1[32];
    const int tid = threadIdx.x, w = tid >> 5, l = tid & 31;
    for (int r = w; r < 20; r += 8) {
        float acc = 0.0f;
        for (int k = l; k < H; k += 32) acc += g_hfinal[k] * w1[r * H + k];
#pragma unroll
        for (int off = 16; off; off >>= 1) acc += __shfl_xor_sync(FULLMASK, acc, off);
        if (l == 0) y1[r] = acc + b1[r];
    }
    __syncthreads();
    if (tid == 0) {
        float o = b2[0];
#pragma unroll
        for (int r = 0; r < 20; r++) o += y1[r] * w2[r];
        out[0] = o;
    }
}

extern "C" void kernel_launch(void* const* d_in, const int* in_sizes, int n_in,
                              void* d_out, int out_size)
{
    const float* x    = (const float*)d_in[0];
    const float* wih0 = (const float*)d_in[1];
    const float* whh0 = (const float*)d_in[2];
    const float* bih0 = (const float*)d_in[3];
    const float* bhh0 = (const float*)d_in[4];
    const float* wih1 = (const float*)d_in[5];
    const float* whh1 = (const float*)d_in[6];
    const float* bih1 = (const float*)d_in[7];
    const float* bhh1 = (const float*)d_in[8];
    const float* w1   = (const float*)d_in[9];
    const float* b1   = (const float*)d_in[10];
    const float* w2   = (const float*)d_in[11];
    const float* b2   = (const float*)d_in[12];
    float* out = (float*)d_out;

    init_kernel<<<1, 256>>>();
    lstm_kernel<0><<<NCTA, NTHREADS>>>(x, wih0, whh0, bih0, bhh0);
    init_kernel<<<1, 256>>>();
    lstm_kernel<1><<<NCTA, NTHREADS>>>(nullptr, wih1, whh1, bih1, bhh1);
    head_kernel<<<1, 256>>>(w1, b1, w2, b2, out);
}